// round 5
// baseline (speedup 1.0000x reference)
#include <cuda_runtime.h>
#include <math.h>

// Problem constants (fixed shapes)
#define NROWS (8 * 4096)   // B*T
#define DD    1024
#define HCC   256
#define HVV   256
#define NTT   64
#define NCC   8
#define TPCC  8
#define GGG   16
#define TTT   4096

// ---------------- scratch (static device globals; no runtime allocation) ----
__device__ float    g_xn[(size_t)NROWS * DD];
__device__ float    g_res[(size_t)NROWS * DD];
__device__ float    g_h[(size_t)NROWS * HCC];
__device__ float    g_h2[(size_t)NROWS * HVV];
__device__ int      g_tidx[NROWS];
__device__ float    g_tw[NROWS];
__device__ unsigned g_sigbits[NTT * 32];       // 64 tiles x 1024 bits
__device__ signed char g_csig[NCC * DD];       // {-1,0,1}

__device__ __forceinline__ float bspline(float t) {
    t = fabsf(t);
    if (t < 1.0f) return (2.0f / 3.0f) - t * t + 0.5f * t * t * t;
    if (t < 2.0f) { float u = 2.0f - t; return (1.0f / 6.0f) * u * u * u; }
    return 0.0f;
}

__device__ __forceinline__ float gelu_exact(float v) {
    return 0.5f * v * (1.0f + erff(v * 0.70710678118654752f));
}

// ---------------- prep: pack sign(directions) and csig ----------------------
__global__ void prep_kernel(const float* __restrict__ dirs) {
    int tid = threadIdx.x;
    // csig = sign(mean over TPC of sign(dirs)) per (cluster, d)
    for (int idx = tid; idx < NCC * DD; idx += blockDim.x) {
        int c = idx / DD, d = idx % DD;
        int s = 0;
        #pragma unroll
        for (int i = 0; i < TPCC; i++) {
            float v = dirs[(size_t)(c * TPCC + i) * DD + d];
            s += (v > 0.0f) ? 1 : ((v < 0.0f) ? -1 : 0);
        }
        g_csig[idx] = (signed char)((s > 0) - (s < 0));
    }
    // sign bits for all 64 tiles
    int lane = tid & 31, wid = tid >> 5;
    int nw = blockDim.x >> 5;
    for (int q = wid; q < NTT * 32; q += nw) {
        int t = q >> 5, w = q & 31;
        float v = dirs[(size_t)t * DD + w * 32 + lane];
        unsigned m = __ballot_sync(0xFFFFFFFFu, v > 0.0f);
        if (lane == 0) g_sigbits[q] = m;
    }
}

// ---------------- LN + content + tile selection (1 row per block) -----------
__global__ __launch_bounds__(256) void ln_content_kernel(
    const float* __restrict__ x, const int* __restrict__ positions,
    const float* __restrict__ ln_g, const float* __restrict__ ln_b)
{
    __shared__ float    s_xn[DD];
    __shared__ unsigned s_bits[NTT * 32];
    __shared__ signed char s_csig[NCC * DD];
    __shared__ float s_content[NTT];
    __shared__ float s_cs[NCC];
    __shared__ float s_red[8], s_red2[8];
    __shared__ float s_mu, s_rstd;

    int row = blockIdx.x;
    int tid = threadIdx.x, lane = tid & 31, wid = tid >> 5;
    const float* xr = x + (size_t)row * DD;

    float4 xv = *(const float4*)(xr + tid * 4);
    float ps  = xv.x + xv.y + xv.z + xv.w;
    float ps2 = xv.x * xv.x + xv.y * xv.y + xv.z * xv.z + xv.w * xv.w;
    #pragma unroll
    for (int o = 16; o; o >>= 1) {
        ps  += __shfl_xor_sync(0xFFFFFFFFu, ps, o);
        ps2 += __shfl_xor_sync(0xFFFFFFFFu, ps2, o);
    }
    if (lane == 0) { s_red[wid] = ps; s_red2[wid] = ps2; }
    __syncthreads();
    if (tid == 0) {
        float s = 0.0f, s2 = 0.0f;
        #pragma unroll
        for (int i = 0; i < 8; i++) { s += s_red[i]; s2 += s_red2[i]; }
        float mu  = s * (1.0f / DD);
        float var = s2 * (1.0f / DD) - mu * mu;
        s_mu = mu;
        s_rstd = rsqrtf(var + 1e-5f);
    }
    // stage bit tables while the reduction result settles (L2-resident)
    for (int i = tid; i < NTT * 32; i += 256) s_bits[i] = __ldg(&g_sigbits[i]);
    for (int i = tid; i < (NCC * DD) / 16; i += 256)
        ((int4*)s_csig)[i] = __ldg(((const int4*)g_csig) + i);
    __syncthreads();

    float mu = s_mu, rstd = s_rstd;
    float4 g4 = *(const float4*)(ln_g + tid * 4);
    float4 b4 = *(const float4*)(ln_b + tid * 4);
    float4 nv;
    nv.x = (xv.x - mu) * rstd * g4.x + b4.x;
    nv.y = (xv.y - mu) * rstd * g4.y + b4.y;
    nv.z = (xv.z - mu) * rstd * g4.z + b4.z;
    nv.w = (xv.w - mu) * rstd * g4.w + b4.w;
    *(float4*)(s_xn + tid * 4) = nv;
    *(float4*)(g_xn + (size_t)row * DD + tid * 4) = nv;
    __syncthreads();

    // content: each warp handles 8 tiles; sign-dot via packed bits
    #pragma unroll
    for (int j = 0; j < 8; j++) {
        int t = wid * 8 + j;
        const unsigned* bw = s_bits + t * 32;
        float acc = 0.0f;
        #pragma unroll
        for (int i = 0; i < 32; i++) {
            float v = s_xn[i * 32 + lane];
            acc += ((bw[i] >> lane) & 1u) ? v : -v;
        }
        #pragma unroll
        for (int o = 16; o; o >>= 1) acc += __shfl_xor_sync(0xFFFFFFFFu, acc, o);
        if (lane == 0) s_content[t] = acc;
    }
    // cluster scores: warp w -> cluster w
    {
        float acc = 0.0f;
        const signed char* cp = s_csig + wid * DD;
        for (int i = lane; i < DD; i += 32) acc += s_xn[i] * (float)cp[i];
        #pragma unroll
        for (int o = 16; o; o >>= 1) acc += __shfl_xor_sync(0xFFFFFFFFu, acc, o);
        if (lane == 0) s_cs[wid] = acc;
    }
    __syncthreads();

    if (tid == 0) {
        float p = (float)positions[row & (TTT - 1)];
        // cluster argmax (first-max semantics, matches jnp.argmax)
        float bestc = -INFINITY; int cidx = 0;
        #pragma unroll
        for (int c = 0; c < NCC; c++) {
            float arg = (p * (8.0f / 4096.0f) - (float)c) * 4.0f; // / w_c=0.25
            float v = s_cs[c] * bspline(arg);
            if (v > bestc) { bestc = v; cidx = c; }
        }
        // tile argmax within the winning cluster (first-max semantics)
        float bestt = -INFINITY; int ti = cidx * TPCC;
        for (int t = cidx * TPCC; t < cidx * TPCC + TPCC; t++) {
            float arg = (p * (64.0f / 4096.0f) - (float)t) * 0.5f; // / SPREAD=2
            float v = s_content[t] * bspline(arg);
            if (v > bestt) { bestt = v; ti = t; }
        }
        g_tidx[row] = ti;
        g_tw[row] = bestt;
    }
}

// ---------------- row finisher: ab GEMV, spline, residual -------------------
__global__ __launch_bounds__(256) void rowfin_kernel(
    const float* __restrict__ Wc2, const float* __restrict__ bc2,
    const float* __restrict__ spline_coeffs, const float* __restrict__ sscale,
    const float* __restrict__ gscale, const float* __restrict__ gshift,
    const float* __restrict__ dirs)
{
    int row = blockIdx.x;
    int tid = threadIdx.x, lane = tid & 31, wid = tid >> 5;
    __shared__ float s_sp;
    int ti = g_tidx[row];

    if (wid == 0) {
        float a0 = 0.0f, a1 = 0.0f;
        const float* hr = g_h + (size_t)row * HCC;
        for (int j = lane; j < HCC; j += 32) {
            float hv = hr[j];
            a0 += hv * Wc2[j * 2 + 0];
            a1 += hv * Wc2[j * 2 + 1];
        }
        #pragma unroll
        for (int o = 16; o; o >>= 1) {
            a0 += __shfl_xor_sync(0xFFFFFFFFu, a0, o);
            a1 += __shfl_xor_sync(0xFFFFFFFFu, a1, o);
        }
        if (lane == 0) {
            float a = tanhf(a0 + bc2[0]);
            float b = tanhf(a1 + bc2[1]);
            int ia = (int)((a + 1.0f) * 8.0f); ia = ia < 0 ? 0 : (ia > GGG - 1 ? GGG - 1 : ia);
            int ib = (int)((b + 1.0f) * 8.0f); ib = ib < 0 ? 0 : (ib > GGG - 1 ? GGG - 1 : ib);
            const float* cp = spline_coeffs + (((size_t)ti * GGG + ia) * GGG + ib) * 3;
            float c0 = cp[0] > 0.3f ? 1.0f : (cp[0] < -0.3f ? -1.0f : 0.0f);
            float c1 = cp[1] > 0.3f ? 1.0f : (cp[1] < -0.3f ? -1.0f : 0.0f);
            float c2 = cp[2] > 0.3f ? 1.0f : (cp[2] < -0.3f ? -1.0f : 0.0f);
            float la = (a + 1.0f - (float)ia * 0.125f) * 8.0f;
            float lb = (b + 1.0f - (float)ib * 0.125f) * 8.0f;
            s_sp = (c0 + c1 * la + c2 * lb) * sscale[ti] * g_tw[row];
        }
    }
    __syncthreads();
    float sp = s_sp;
    int d = tid * 4;
    size_t base = (size_t)row * DD + d;
    size_t tb = (size_t)ti * DD + d;
    float4 dir = *(const float4*)(dirs + tb);
    float4 gs  = *(const float4*)(gscale + tb);
    float4 gb  = *(const float4*)(gshift + tb);
    float4 xn  = *(const float4*)(g_xn + base);
    float4 r;
    r.x = xn.x - (sp * dir.x - gb.x) / (gs.x + 1e-6f);
    r.y = xn.y - (sp * dir.y - gb.y) / (gs.y + 1e-6f);
    r.z = xn.z - (sp * dir.z - gb.z) / (gs.z + 1e-6f);
    r.w = xn.w - (sp * dir.w - gb.w) / (gs.w + 1e-6f);
    *(float4*)(g_res + base) = r;
}

// ---- tiled fp32 GEMM (128x128x16, 256 thr, 8x8/thread, sw-pipelined) ------
// MODE 1: C=g_h   = gelu((xn*gauge_s+gauge_b) @ Bm + bias)        [N=256,  K=1024]
// MODE 3: C=g_h2  = gelu(g_res @ Bm + bias)                       [N=256,  K=1024]
// MODE 4: out     = x + os*((xn-res) + sig(gate)*(g_h2@Bm + bias)) [N=1024, K=256]
template <int MODE, int N, int K>
__global__ __launch_bounds__(256) void gemm_kernel(
    const float* __restrict__ Bm, const float* __restrict__ bias,
    const float* __restrict__ gscale, const float* __restrict__ gshift,
    const float* __restrict__ x, const float* __restrict__ gate,
    const float* __restrict__ oscale, float* __restrict__ out)
{
    __shared__ float As[16][128];
    __shared__ float Bs[16][128];
    int tid = threadIdx.x;
    int bm = blockIdx.y * 128, bn = blockIdx.x * 128;
    // A staging: thread loads row aRow, cols [aCol, aCol+8) (two float4)
    int aRow = tid >> 1, aCol = (tid & 1) * 8;
    // B staging: thread loads row bRow, cols [bCol, bCol+8) (two float4)
    int bRow = tid >> 4, bCol = (tid & 15) * 8;

    const float* A = (MODE == 1) ? g_xn : ((MODE == 3) ? g_res : g_h2);
    const float* Ap = A + (size_t)(bm + aRow) * K + aCol;
    const float* Bp = Bm + (size_t)bRow * N + bn + bCol;

    const float* gsp = nullptr;
    const float* gbp = nullptr;
    if (MODE == 1) {
        int ti = g_tidx[bm + aRow];
        gsp = gscale + (size_t)ti * DD + aCol;
        gbp = gshift + (size_t)ti * DD + aCol;
    }

    float acc[8][8];
    #pragma unroll
    for (int i = 0; i < 8; i++)
        #pragma unroll
        for (int j = 0; j < 8; j++) acc[i][j] = 0.0f;

    int tx = tid & 15, ty = tid >> 4;

    float4 avr[2], bvr[2];

    // prefetch tile 0 into registers (gauge fused for MODE 1)
    #pragma unroll
    for (int h = 0; h < 2; h++) {
        float4 av = *(const float4*)(Ap + h * 4);
        if (MODE == 1) {
            float4 gs = *(const float4*)(gsp + h * 4);
            float4 gb = *(const float4*)(gbp + h * 4);
            av.x = av.x * gs.x + gb.x;
            av.y = av.y * gs.y + gb.y;
            av.z = av.z * gs.z + gb.z;
            av.w = av.w * gs.w + gb.w;
        }
        avr[h] = av;
        bvr[h] = *(const float4*)(Bp + (size_t)(h * 4) * 0 + h * 4);  // placeholder, fixed below
    }
    bvr[0] = *(const float4*)(Bp);
    bvr[1] = *(const float4*)(Bp + 4);

    for (int k0 = 0; k0 < K; k0 += 16) {
        // commit staged registers to shared memory
        #pragma unroll
        for (int h = 0; h < 2; h++) {
            int c = aCol + h * 4;
            As[c + 0][aRow] = avr[h].x;
            As[c + 1][aRow] = avr[h].y;
            As[c + 2][aRow] = avr[h].z;
            As[c + 3][aRow] = avr[h].w;
        }
        *(float4*)&Bs[bRow][bCol]     = bvr[0];
        *(float4*)&Bs[bRow][bCol + 4] = bvr[1];
        __syncthreads();

        // prefetch next tile into registers (overlaps with compute below)
        int kn = k0 + 16;
        if (kn < K) {
            #pragma unroll
            for (int h = 0; h < 2; h++) {
                float4 av = *(const float4*)(Ap + kn + h * 4);
                if (MODE == 1) {
                    float4 gs = *(const float4*)(gsp + kn + h * 4);
                    float4 gb = *(const float4*)(gbp + kn + h * 4);
                    av.x = av.x * gs.x + gb.x;
                    av.y = av.y * gs.y + gb.y;
                    av.z = av.z * gs.z + gb.z;
                    av.w = av.w * gs.w + gb.w;
                }
                avr[h] = av;
            }
            bvr[0] = *(const float4*)(Bp + (size_t)kn * N);
            bvr[1] = *(const float4*)(Bp + (size_t)kn * N + 4);
        }

        #pragma unroll
        for (int kk = 0; kk < 16; kk++) {
            float ra[8], rb[8];
            *(float4*)(ra)     = *(const float4*)&As[kk][ty * 8];
            *(float4*)(ra + 4) = *(const float4*)&As[kk][ty * 8 + 4];
            *(float4*)(rb)     = *(const float4*)&Bs[kk][tx * 8];
            *(float4*)(rb + 4) = *(const float4*)&Bs[kk][tx * 8 + 4];
            #pragma unroll
            for (int i = 0; i < 8; i++)
                #pragma unroll
                for (int j = 0; j < 8; j++)
                    acc[i][j] += ra[i] * rb[j];
        }
        __syncthreads();
    }

    if (MODE == 1 || MODE == 3) {
        float* C = (MODE == 1) ? g_h : g_h2;
        #pragma unroll
        for (int i = 0; i < 8; i++) {
            int r = bm + ty * 8 + i;
            float* cr = C + (size_t)r * N + bn + tx * 8;
            #pragma unroll
            for (int j = 0; j < 8; j++) {
                float v = acc[i][j] + bias[bn + tx * 8 + j];
                cr[j] = gelu_exact(v);
            }
        }
    } else {
        float gv = 1.0f / (1.0f + expf(-gate[0]));
        float os = oscale[0];
        #pragma unroll
        for (int i = 0; i < 8; i++) {
            int r = bm + ty * 8 + i;
            size_t base = (size_t)r * N + bn + tx * 8; // N == DD here
            #pragma unroll
            for (int j = 0; j < 8; j++) {
                size_t idx = base + j;
                float o = (g_xn[idx] - g_res[idx]) + gv * (acc[i][j] + bias[bn + tx * 8 + j]);
                out[idx] = x[idx] + os * o;
            }
        }
    }
}

// ---------------- launcher --------------------------------------------------
extern "C" void kernel_launch(void* const* d_in, const int* in_sizes, int n_in,
                              void* d_out, int out_size) {
    const float* x     = (const float*)d_in[0];
    const int*   pos   = (const int*)d_in[1];
    const float* ln_g  = (const float*)d_in[2];
    const float* ln_b  = (const float*)d_in[3];
    const float* Wc1   = (const float*)d_in[4];
    const float* bc1   = (const float*)d_in[5];
    const float* Wc2   = (const float*)d_in[6];
    const float* bc2   = (const float*)d_in[7];
    const float* dirs  = (const float*)d_in[8];
    const float* spl   = (const float*)d_in[9];
    const float* sscal = (const float*)d_in[10];
    const float* gsc   = (const float*)d_in[11];
    const float* gsh   = (const float*)d_in[12];
    const float* Wv1   = (const float*)d_in[13];
    const float* bv1   = (const float*)d_in[14];
    const float* Wv2   = (const float*)d_in[15];
    const float* bv2   = (const float*)d_in[16];
    const float* gate  = (const float*)d_in[17];
    const float* oscal = (const float*)d_in[18];
    float* out = (float*)d_out;

    prep_kernel<<<1, 256>>>(dirs);
    ln_content_kernel<<<NROWS, 256>>>(x, pos, ln_g, ln_b);

    dim3 g1(HCC / 128, NROWS / 128);
    gemm_kernel<1, HCC, DD><<<g1, 256>>>(Wc1, bc1, gsc, gsh, nullptr, nullptr, nullptr, nullptr);

    rowfin_kernel<<<NROWS, 256>>>(Wc2, bc2, spl, sscal, gsc, gsh, dirs);

    dim3 g3(HVV / 128, NROWS / 128);
    gemm_kernel<3, HVV, DD><<<g3, 256>>>(Wv1, bv1, nullptr, nullptr, nullptr, nullptr, nullptr, nullptr);

    dim3 g4(DD / 128, NROWS / 128);
    gemm_kernel<4, DD, HVV><<<g4, 256>>>(Wv2, bv2, nullptr, nullptr, x, gate, oscal, out);
}

// round 10
// speedup vs baseline: 2.8942x; 2.8942x over previous
#include <cuda_runtime.h>
#include <cuda_bf16.h>
#include <math.h>

// Problem constants (fixed shapes)
#define NROWS (8 * 4096)   // B*T
#define DD    1024
#define HCC   256
#define HVV   256
#define NTT   64
#define NCC   8
#define TPCC  8
#define GGG   16
#define TTT   4096

// ---------------- scratch (static device globals; no runtime allocation) ----
__device__ float         g_xn[(size_t)NROWS * DD];
__device__ float         g_d[(size_t)NROWS * DD];       // out_sp (pre-vortex)
__device__ float         g_h[(size_t)NROWS * HCC];
__device__ __nv_bfloat16 g_ah[(size_t)NROWS * DD];      // hi(gauge(xn))
__device__ __nv_bfloat16 g_al[(size_t)NROWS * DD];      // lo(gauge(xn))
__device__ __nv_bfloat16 g_resb[(size_t)NROWS * DD];    // res in bf16 (GEMM3 A)
__device__ __nv_bfloat16 g_h2b[(size_t)NROWS * HVV];    // gelu(h2) bf16 (GEMM4 A)
__device__ __nv_bfloat16 g_Wc1h[HCC * DD];              // [256][1024] n-major hi
__device__ __nv_bfloat16 g_Wc1l[HCC * DD];              // [256][1024] n-major lo
__device__ __nv_bfloat16 g_Wv1t[HVV * DD];              // [256][1024] n-major
__device__ __nv_bfloat16 g_Wv2t[DD * HVV];              // [1024][256] n-major
__device__ int           g_tidx[NROWS];
__device__ float         g_tw[NROWS];
__device__ unsigned      g_sigbits[NTT * 32];
__device__ signed char   g_csig[NCC * DD];

__device__ __forceinline__ float bspline(float t) {
    t = fabsf(t);
    if (t < 1.0f) return (2.0f / 3.0f) - t * t + 0.5f * t * t * t;
    if (t < 2.0f) { float u = 2.0f - t; return (1.0f / 6.0f) * u * u * u; }
    return 0.0f;
}

__device__ __forceinline__ float gelu_exact(float v) {
    return 0.5f * v * (1.0f + erff(v * 0.70710678118654752f));
}

__device__ __forceinline__ void mma16816(float* d, const unsigned* a,
                                         const unsigned* b) {
    asm volatile(
        "mma.sync.aligned.m16n8k16.row.col.f32.bf16.bf16.f32 "
        "{%0,%1,%2,%3}, {%4,%5,%6,%7}, {%8,%9}, {%0,%1,%2,%3};\n"
        : "+f"(d[0]), "+f"(d[1]), "+f"(d[2]), "+f"(d[3])
        : "r"(a[0]), "r"(a[1]), "r"(a[2]), "r"(a[3]), "r"(b[0]), "r"(b[1]));
}

// ---------------- prep: pack sign(directions) and csig ----------------------
__global__ void prep_kernel(const float* __restrict__ dirs) {
    int tid = threadIdx.x;
    for (int idx = tid; idx < NCC * DD; idx += blockDim.x) {
        int c = idx / DD, d = idx % DD;
        int s = 0;
        #pragma unroll
        for (int i = 0; i < TPCC; i++) {
            float v = dirs[(size_t)(c * TPCC + i) * DD + d];
            s += (v > 0.0f) ? 1 : ((v < 0.0f) ? -1 : 0);
        }
        g_csig[idx] = (signed char)((s > 0) - (s < 0));
    }
    int lane = tid & 31, wid = tid >> 5;
    int nw = blockDim.x >> 5;
    for (int q = wid; q < NTT * 32; q += nw) {
        int t = q >> 5, w = q & 31;
        float v = dirs[(size_t)t * DD + w * 32 + lane];
        unsigned m = __ballot_sync(0xFFFFFFFFu, v > 0.0f);
        if (lane == 0) g_sigbits[q] = m;
    }
}

// ------- weight conversion: Wv1/Wv2 -> bf16 transposed, Wc1 -> split --------
__global__ void convert_weights_kernel(const float* __restrict__ Wv1,
                                       const float* __restrict__ Wv2,
                                       const float* __restrict__ Wc1) {
    int i = blockIdx.x * blockDim.x + threadIdx.x;  // 0 .. 262143
    if (i < HVV * DD) {
        int n = i >> 10, k = i & 1023;
        g_Wv1t[i] = __float2bfloat16(Wv1[(size_t)k * HVV + n]);
        int n2 = i >> 8, k2 = i & 255;
        g_Wv2t[i] = __float2bfloat16(Wv2[(size_t)k2 * DD + n2]);
        // Wc1 split: g_Wc1h/l[n][k] = split(Wc1[k][n])
        float w = Wc1[(size_t)k * HCC + n];
        __nv_bfloat16 hi = __float2bfloat16(w);
        g_Wc1h[i] = hi;
        g_Wc1l[i] = __float2bfloat16(w - __bfloat162float(hi));
    }
}

// ---- LN + content + tile selection + gauge-split (1 row per block) ---------
__global__ __launch_bounds__(256) void ln_content_kernel(
    const float* __restrict__ x, const int* __restrict__ positions,
    const float* __restrict__ ln_g, const float* __restrict__ ln_b,
    const float* __restrict__ gscale, const float* __restrict__ gshift)
{
    __shared__ float    s_xn[DD];
    __shared__ unsigned s_bits[NTT * 32];
    __shared__ signed char s_csig[NCC * DD];
    __shared__ float s_content[NTT];
    __shared__ float s_cs[NCC];
    __shared__ float s_red[8], s_red2[8];
    __shared__ float s_mu, s_rstd;
    __shared__ int   s_ti;

    int row = blockIdx.x;
    int tid = threadIdx.x, lane = tid & 31, wid = tid >> 5;
    const float* xr = x + (size_t)row * DD;

    float4 xv = *(const float4*)(xr + tid * 4);
    float ps  = xv.x + xv.y + xv.z + xv.w;
    float ps2 = xv.x * xv.x + xv.y * xv.y + xv.z * xv.z + xv.w * xv.w;
    #pragma unroll
    for (int o = 16; o; o >>= 1) {
        ps  += __shfl_xor_sync(0xFFFFFFFFu, ps, o);
        ps2 += __shfl_xor_sync(0xFFFFFFFFu, ps2, o);
    }
    if (lane == 0) { s_red[wid] = ps; s_red2[wid] = ps2; }
    __syncthreads();
    if (tid == 0) {
        float s = 0.0f, s2 = 0.0f;
        #pragma unroll
        for (int i = 0; i < 8; i++) { s += s_red[i]; s2 += s_red2[i]; }
        float mu  = s * (1.0f / DD);
        float var = s2 * (1.0f / DD) - mu * mu;
        s_mu = mu;
        s_rstd = rsqrtf(var + 1e-5f);
    }
    for (int i = tid; i < NTT * 32; i += 256) s_bits[i] = __ldg(&g_sigbits[i]);
    for (int i = tid; i < (NCC * DD) / 16; i += 256)
        ((int4*)s_csig)[i] = __ldg(((const int4*)g_csig) + i);
    __syncthreads();

    float mu = s_mu, rstd = s_rstd;
    float4 g4 = *(const float4*)(ln_g + tid * 4);
    float4 b4 = *(const float4*)(ln_b + tid * 4);
    float4 nv;
    nv.x = (xv.x - mu) * rstd * g4.x + b4.x;
    nv.y = (xv.y - mu) * rstd * g4.y + b4.y;
    nv.z = (xv.z - mu) * rstd * g4.z + b4.z;
    nv.w = (xv.w - mu) * rstd * g4.w + b4.w;
    *(float4*)(s_xn + tid * 4) = nv;
    *(float4*)(g_xn + (size_t)row * DD + tid * 4) = nv;
    __syncthreads();

    #pragma unroll
    for (int j = 0; j < 8; j++) {
        int t = wid * 8 + j;
        const unsigned* bw = s_bits + t * 32;
        float acc = 0.0f;
        #pragma unroll
        for (int i = 0; i < 32; i++) {
            float v = s_xn[i * 32 + lane];
            acc += ((bw[i] >> lane) & 1u) ? v : -v;
        }
        #pragma unroll
        for (int o = 16; o; o >>= 1) acc += __shfl_xor_sync(0xFFFFFFFFu, acc, o);
        if (lane == 0) s_content[t] = acc;
    }
    {
        float acc = 0.0f;
        const signed char* cp = s_csig + wid * DD;
        for (int i = lane; i < DD; i += 32) acc += s_xn[i] * (float)cp[i];
        #pragma unroll
        for (int o = 16; o; o >>= 1) acc += __shfl_xor_sync(0xFFFFFFFFu, acc, o);
        if (lane == 0) s_cs[wid] = acc;
    }
    __syncthreads();

    if (tid == 0) {
        float p = (float)positions[row & (TTT - 1)];
        float bestc = -INFINITY; int cidx = 0;
        #pragma unroll
        for (int c = 0; c < NCC; c++) {
            float arg = (p * (8.0f / 4096.0f) - (float)c) * 4.0f;
            float v = s_cs[c] * bspline(arg);
            if (v > bestc) { bestc = v; cidx = c; }
        }
        float bestt = -INFINITY; int ti = cidx * TPCC;
        for (int t = cidx * TPCC; t < cidx * TPCC + TPCC; t++) {
            float arg = (p * (64.0f / 4096.0f) - (float)t) * 0.5f;
            float v = s_content[t] * bspline(arg);
            if (v > bestt) { bestt = v; ti = t; }
        }
        g_tidx[row] = ti;
        g_tw[row] = bestt;
        s_ti = ti;
    }
    __syncthreads();

    // gauge transform + hi/lo bf16 split (uses registers, no smem hazard)
    {
        int ti = s_ti;
        int d = tid * 4;
        size_t base = (size_t)row * DD + d;
        size_t tb = (size_t)ti * DD + d;
        float4 gs = *(const float4*)(gscale + tb);
        float4 gb = *(const float4*)(gshift + tb);
        float v0 = nv.x * gs.x + gb.x;
        float v1 = nv.y * gs.y + gb.y;
        float v2 = nv.z * gs.z + gb.z;
        float v3 = nv.w * gs.w + gb.w;
        __nv_bfloat16 h0 = __float2bfloat16(v0), h1 = __float2bfloat16(v1);
        __nv_bfloat16 h2 = __float2bfloat16(v2), h3 = __float2bfloat16(v3);
        __nv_bfloat162 hp0; hp0.x = h0; hp0.y = h1;
        __nv_bfloat162 hp1; hp1.x = h2; hp1.y = h3;
        *(__nv_bfloat162*)(g_ah + base)     = hp0;
        *(__nv_bfloat162*)(g_ah + base + 2) = hp1;
        __nv_bfloat162 lp0 = __floats2bfloat162_rn(v0 - __bfloat162float(h0),
                                                   v1 - __bfloat162float(h1));
        __nv_bfloat162 lp1 = __floats2bfloat162_rn(v2 - __bfloat162float(h2),
                                                   v3 - __bfloat162float(h3));
        *(__nv_bfloat162*)(g_al + base)     = lp0;
        *(__nv_bfloat162*)(g_al + base + 2) = lp1;
    }
}

// ---------------- row finisher: ab GEMV, spline, out_sp + res(bf16) ---------
__global__ __launch_bounds__(256) void rowfin_kernel(
    const float* __restrict__ Wc2, const float* __restrict__ bc2,
    const float* __restrict__ spline_coeffs, const float* __restrict__ sscale,
    const float* __restrict__ gscale, const float* __restrict__ gshift,
    const float* __restrict__ dirs)
{
    int row = blockIdx.x;
    int tid = threadIdx.x, lane = tid & 31, wid = tid >> 5;
    __shared__ float s_sp;
    int ti = g_tidx[row];

    if (wid == 0) {
        float a0 = 0.0f, a1 = 0.0f;
        const float* hr = g_h + (size_t)row * HCC;
        for (int j = lane; j < HCC; j += 32) {
            float hv = hr[j];
            a0 += hv * Wc2[j * 2 + 0];
            a1 += hv * Wc2[j * 2 + 1];
        }
        #pragma unroll
        for (int o = 16; o; o >>= 1) {
            a0 += __shfl_xor_sync(0xFFFFFFFFu, a0, o);
            a1 += __shfl_xor_sync(0xFFFFFFFFu, a1, o);
        }
        if (lane == 0) {
            float a = tanhf(a0 + bc2[0]);
            float b = tanhf(a1 + bc2[1]);
            int ia = (int)((a + 1.0f) * 8.0f); ia = ia < 0 ? 0 : (ia > GGG - 1 ? GGG - 1 : ia);
            int ib = (int)((b + 1.0f) * 8.0f); ib = ib < 0 ? 0 : (ib > GGG - 1 ? GGG - 1 : ib);
            const float* cp = spline_coeffs + (((size_t)ti * GGG + ia) * GGG + ib) * 3;
            float c0 = cp[0] > 0.3f ? 1.0f : (cp[0] < -0.3f ? -1.0f : 0.0f);
            float c1 = cp[1] > 0.3f ? 1.0f : (cp[1] < -0.3f ? -1.0f : 0.0f);
            float c2 = cp[2] > 0.3f ? 1.0f : (cp[2] < -0.3f ? -1.0f : 0.0f);
            float la = (a + 1.0f - (float)ia * 0.125f) * 8.0f;
            float lb = (b + 1.0f - (float)ib * 0.125f) * 8.0f;
            s_sp = (c0 + c1 * la + c2 * lb) * sscale[ti] * g_tw[row];
        }
    }
    __syncthreads();
    float sp = s_sp;
    int d = tid * 4;
    size_t base = (size_t)row * DD + d;
    size_t tb = (size_t)ti * DD + d;
    float4 dir = *(const float4*)(dirs + tb);
    float4 gs  = *(const float4*)(gscale + tb);
    float4 gb  = *(const float4*)(gshift + tb);
    float4 xn  = *(const float4*)(g_xn + base);
    float4 o;
    o.x = (sp * dir.x - gb.x) / (gs.x + 1e-6f);
    o.y = (sp * dir.y - gb.y) / (gs.y + 1e-6f);
    o.z = (sp * dir.z - gb.z) / (gs.z + 1e-6f);
    o.w = (sp * dir.w - gb.w) / (gs.w + 1e-6f);
    *(float4*)(g_d + base) = o;
    __nv_bfloat162 r01 = __floats2bfloat162_rn(xn.x - o.x, xn.y - o.y);
    __nv_bfloat162 r23 = __floats2bfloat162_rn(xn.z - o.z, xn.w - o.w);
    *(__nv_bfloat162*)(g_resb + base)     = r01;
    *(__nv_bfloat162*)(g_resb + base + 2) = r23;
}

// ---- GEMM1 split-bf16 3-product: h = gelu(Ah*Wh + Al*Wh + Ah*Wl + bias) ----
// [M=NROWS, N=256, K=1024]; 128x128 tile, kchunk 32, 8 warps (64x32 each)
__global__ __launch_bounds__(256) void gemm1split_kernel(
    const float* __restrict__ bias)
{
    constexpr int N = HCC, K = DD, KP = 40;
    __shared__ alignas(16) __nv_bfloat16 Ahs[128 * KP];
    __shared__ alignas(16) __nv_bfloat16 Als[128 * KP];
    __shared__ alignas(16) __nv_bfloat16 Bhs[128 * KP];
    __shared__ alignas(16) __nv_bfloat16 Bls[128 * KP];

    int tid = threadIdx.x;
    int lane = tid & 31, wid = tid >> 5;
    int g = lane >> 2, t4 = lane & 3;
    int wm = (wid >> 2) * 64;
    int wn = (wid & 3) * 32;
    int bm = blockIdx.y * 128, bn = blockIdx.x * 128;

    int lrow = tid >> 1, lcol = (tid & 1) * 16;
    const __nv_bfloat16* Ahp = g_ah + (size_t)(bm + lrow) * K + lcol;
    const __nv_bfloat16* Alp = g_al + (size_t)(bm + lrow) * K + lcol;
    const __nv_bfloat16* Bhp = g_Wc1h + (size_t)(bn + lrow) * K + lcol;
    const __nv_bfloat16* Blp = g_Wc1l + (size_t)(bn + lrow) * K + lcol;

    float acc[4][4][4];
    #pragma unroll
    for (int mi = 0; mi < 4; mi++)
        #pragma unroll
        for (int ni = 0; ni < 4; ni++)
            #pragma unroll
            for (int e = 0; e < 4; e++) acc[mi][ni][e] = 0.0f;

    uint4 pah0 = *(const uint4*)(Ahp),      pah1 = *(const uint4*)(Ahp + 8);
    uint4 pal0 = *(const uint4*)(Alp),      pal1 = *(const uint4*)(Alp + 8);
    uint4 pbh0 = *(const uint4*)(Bhp),      pbh1 = *(const uint4*)(Bhp + 8);
    uint4 pbl0 = *(const uint4*)(Blp),      pbl1 = *(const uint4*)(Blp + 8);

    for (int k0 = 0; k0 < K; k0 += 32) {
        *(uint4*)&Ahs[lrow * KP + lcol]     = pah0;
        *(uint4*)&Ahs[lrow * KP + lcol + 8] = pah1;
        *(uint4*)&Als[lrow * KP + lcol]     = pal0;
        *(uint4*)&Als[lrow * KP + lcol + 8] = pal1;
        *(uint4*)&Bhs[lrow * KP + lcol]     = pbh0;
        *(uint4*)&Bhs[lrow * KP + lcol + 8] = pbh1;
        *(uint4*)&Bls[lrow * KP + lcol]     = pbl0;
        *(uint4*)&Bls[lrow * KP + lcol + 8] = pbl1;
        __syncthreads();

        int kn = k0 + 32;
        if (kn < K) {
            pah0 = *(const uint4*)(Ahp + kn); pah1 = *(const uint4*)(Ahp + kn + 8);
            pal0 = *(const uint4*)(Alp + kn); pal1 = *(const uint4*)(Alp + kn + 8);
            pbh0 = *(const uint4*)(Bhp + kn); pbh1 = *(const uint4*)(Bhp + kn + 8);
            pbl0 = *(const uint4*)(Blp + kn); pbl1 = *(const uint4*)(Blp + kn + 8);
        }

        #pragma unroll
        for (int s = 0; s < 2; s++) {
            int kb = s * 16 + 2 * t4;
            unsigned ah[4][4], al[4][4];
            #pragma unroll
            for (int mi = 0; mi < 4; mi++) {
                const __nv_bfloat16* ph = &Ahs[(wm + mi * 16 + g) * KP + kb];
                ah[mi][0] = *(const unsigned*)(ph);
                ah[mi][1] = *(const unsigned*)(ph + 8 * KP);
                ah[mi][2] = *(const unsigned*)(ph + 8);
                ah[mi][3] = *(const unsigned*)(ph + 8 * KP + 8);
                const __nv_bfloat16* pl = &Als[(wm + mi * 16 + g) * KP + kb];
                al[mi][0] = *(const unsigned*)(pl);
                al[mi][1] = *(const unsigned*)(pl + 8 * KP);
                al[mi][2] = *(const unsigned*)(pl + 8);
                al[mi][3] = *(const unsigned*)(pl + 8 * KP + 8);
            }
            unsigned bh[4][2], bl[4][2];
            #pragma unroll
            for (int ni = 0; ni < 4; ni++) {
                const __nv_bfloat16* ph = &Bhs[(wn + ni * 8 + g) * KP + kb];
                bh[ni][0] = *(const unsigned*)(ph);
                bh[ni][1] = *(const unsigned*)(ph + 8);
                const __nv_bfloat16* pl = &Bls[(wn + ni * 8 + g) * KP + kb];
                bl[ni][0] = *(const unsigned*)(pl);
                bl[ni][1] = *(const unsigned*)(pl + 8);
            }
            #pragma unroll
            for (int mi = 0; mi < 4; mi++)
                #pragma unroll
                for (int ni = 0; ni < 4; ni++) {
                    mma16816(acc[mi][ni], ah[mi], bh[ni]);
                    mma16816(acc[mi][ni], al[mi], bh[ni]);
                    mma16816(acc[mi][ni], ah[mi], bl[ni]);
                }
        }
        __syncthreads();
    }

    #pragma unroll
    for (int mi = 0; mi < 4; mi++) {
        #pragma unroll
        for (int ni = 0; ni < 4; ni++) {
            int r0 = bm + wm + mi * 16 + g;
            int c  = bn + wn + ni * 8 + 2 * t4;
            float b0 = bias[c], b1 = bias[c + 1];
            float2 v0, v1;
            v0.x = gelu_exact(acc[mi][ni][0] + b0);
            v0.y = gelu_exact(acc[mi][ni][1] + b1);
            v1.x = gelu_exact(acc[mi][ni][2] + b0);
            v1.y = gelu_exact(acc[mi][ni][3] + b1);
            *(float2*)(g_h + (size_t)r0 * N + c)       = v0;
            *(float2*)(g_h + (size_t)(r0 + 8) * N + c) = v1;
        }
    }
}

// ---- bf16 tensor-core GEMM: 128x128 tile, kchunk 32, 8 warps (64x32 each) --
// MODE 3: g_h2b = bf16(gelu(g_resb @ Wv1t^T + bv1))   [N=256,  K=1024]
// MODE 4: out = x + os*(g_d + gv*(g_h2b @ Wv2t^T + bv2))  [N=1024, K=256]
template <int MODE, int N, int K>
__global__ __launch_bounds__(256) void bf16gemm_kernel(
    const __nv_bfloat16* __restrict__ A,   // [NROWS][K]
    const __nv_bfloat16* __restrict__ Bt,  // [N][K]
    const float* __restrict__ bias,
    const float* __restrict__ x, const float* __restrict__ gate,
    const float* __restrict__ oscale, float* __restrict__ out)
{
    constexpr int KP = 40;
    __shared__ alignas(16) __nv_bfloat16 As[128 * KP];
    __shared__ alignas(16) __nv_bfloat16 Bs[128 * KP];

    int tid = threadIdx.x;
    int lane = tid & 31, wid = tid >> 5;
    int g = lane >> 2, t4 = lane & 3;
    int wm = (wid >> 2) * 64;
    int wn = (wid & 3) * 32;
    int bm = blockIdx.y * 128, bn = blockIdx.x * 128;

    int lrow = tid >> 1, lcol = (tid & 1) * 16;
    const __nv_bfloat16* Ap = A + (size_t)(bm + lrow) * K + lcol;
    const __nv_bfloat16* Bp = Bt + (size_t)(bn + lrow) * K + lcol;

    float acc[4][4][4];
    #pragma unroll
    for (int mi = 0; mi < 4; mi++)
        #pragma unroll
        for (int ni = 0; ni < 4; ni++)
            #pragma unroll
            for (int e = 0; e < 4; e++) acc[mi][ni][e] = 0.0f;

    uint4 pa0 = *(const uint4*)(Ap);
    uint4 pa1 = *(const uint4*)(Ap + 8);
    uint4 pb0 = *(const uint4*)(Bp);
    uint4 pb1 = *(const uint4*)(Bp + 8);

    for (int k0 = 0; k0 < K; k0 += 32) {
        *(uint4*)&As[lrow * KP + lcol]     = pa0;
        *(uint4*)&As[lrow * KP + lcol + 8] = pa1;
        *(uint4*)&Bs[lrow * KP + lcol]     = pb0;
        *(uint4*)&Bs[lrow * KP + lcol + 8] = pb1;
        __syncthreads();

        int kn = k0 + 32;
        if (kn < K) {
            pa0 = *(const uint4*)(Ap + kn);
            pa1 = *(const uint4*)(Ap + kn + 8);
            pb0 = *(const uint4*)(Bp + kn);
            pb1 = *(const uint4*)(Bp + kn + 8);
        }

        #pragma unroll
        for (int s = 0; s < 2; s++) {
            int kb = s * 16 + 2 * t4;
            unsigned afr[4][4];
            #pragma unroll
            for (int mi = 0; mi < 4; mi++) {
                const __nv_bfloat16* p = &As[(wm + mi * 16 + g) * KP + kb];
                afr[mi][0] = *(const unsigned*)(p);
                afr[mi][1] = *(const unsigned*)(p + 8 * KP);
                afr[mi][2] = *(const unsigned*)(p + 8);
                afr[mi][3] = *(const unsigned*)(p + 8 * KP + 8);
            }
            unsigned bfr[4][2];
            #pragma unroll
            for (int ni = 0; ni < 4; ni++) {
                const __nv_bfloat16* p = &Bs[(wn + ni * 8 + g) * KP + kb];
                bfr[ni][0] = *(const unsigned*)(p);
                bfr[ni][1] = *(const unsigned*)(p + 8);
            }
            #pragma unroll
            for (int mi = 0; mi < 4; mi++)
                #pragma unroll
                for (int ni = 0; ni < 4; ni++)
                    mma16816(acc[mi][ni], afr[mi], bfr[ni]);
        }
        __syncthreads();
    }

    float gv = 0.0f, os = 0.0f;
    if (MODE == 4) {
        gv = 1.0f / (1.0f + expf(-gate[0]));
        os = oscale[0];
    }
    #pragma unroll
    for (int mi = 0; mi < 4; mi++) {
        #pragma unroll
        for (int ni = 0; ni < 4; ni++) {
            int r0 = bm + wm + mi * 16 + g;
            int c  = bn + wn + ni * 8 + 2 * t4;
            float b0 = bias[c], b1 = bias[c + 1];
            if (MODE == 3) {
                float v0 = gelu_exact(acc[mi][ni][0] + b0);
                float v1 = gelu_exact(acc[mi][ni][1] + b1);
                float v2 = gelu_exact(acc[mi][ni][2] + b0);
                float v3 = gelu_exact(acc[mi][ni][3] + b1);
                *(__nv_bfloat162*)(g_h2b + (size_t)r0 * N + c) =
                    __floats2bfloat162_rn(v0, v1);
                *(__nv_bfloat162*)(g_h2b + (size_t)(r0 + 8) * N + c) =
                    __floats2bfloat162_rn(v2, v3);
            } else {
                size_t i0 = (size_t)r0 * N + c;
                size_t i1 = (size_t)(r0 + 8) * N + c;
                float2 x0 = *(const float2*)(x + i0);
                float2 x1 = *(const float2*)(x + i1);
                float2 d0 = *(const float2*)(g_d + i0);
                float2 d1 = *(const float2*)(g_d + i1);
                float2 o0, o1;
                o0.x = x0.x + os * (d0.x + gv * (acc[mi][ni][0] + b0));
                o0.y = x0.y + os * (d0.y + gv * (acc[mi][ni][1] + b1));
                o1.x = x1.x + os * (d1.x + gv * (acc[mi][ni][2] + b0));
                o1.y = x1.y + os * (d1.y + gv * (acc[mi][ni][3] + b1));
                *(float2*)(out + i0) = o0;
                *(float2*)(out + i1) = o1;
            }
        }
    }
}

// ---------------- launcher --------------------------------------------------
extern "C" void kernel_launch(void* const* d_in, const int* in_sizes, int n_in,
                              void* d_out, int out_size) {
    const float* x     = (const float*)d_in[0];
    const int*   pos   = (const int*)d_in[1];
    const float* ln_g  = (const float*)d_in[2];
    const float* ln_b  = (const float*)d_in[3];
    const float* Wc1   = (const float*)d_in[4];
    const float* bc1   = (const float*)d_in[5];
    const float* Wc2   = (const float*)d_in[6];
    const float* bc2   = (const float*)d_in[7];
    const float* dirs  = (const float*)d_in[8];
    const float* spl   = (const float*)d_in[9];
    const float* sscal = (const float*)d_in[10];
    const float* gsc   = (const float*)d_in[11];
    const float* gsh   = (const float*)d_in[12];
    const float* Wv1   = (const float*)d_in[13];
    const float* bv1   = (const float*)d_in[14];
    const float* Wv2   = (const float*)d_in[15];
    const float* bv2   = (const float*)d_in[16];
    const float* gate  = (const float*)d_in[17];
    const float* oscal = (const float*)d_in[18];
    float* out = (float*)d_out;

    prep_kernel<<<1, 256>>>(dirs);
    convert_weights_kernel<<<(HVV * DD + 255) / 256, 256>>>(Wv1, Wv2, Wc1);
    ln_content_kernel<<<NROWS, 256>>>(x, pos, ln_g, ln_b, gsc, gsh);

    dim3 g1(HCC / 128, NROWS / 128);
    gemm1split_kernel<<<g1, 256>>>(bc1);

    rowfin_kernel<<<NROWS, 256>>>(Wc2, bc2, spl, sscal, gsc, gsh, dirs);

    __nv_bfloat16* resb;  cudaGetSymbolAddress((void**)&resb, g_resb);
    __nv_bfloat16* h2b;   cudaGetSymbolAddress((void**)&h2b, g_h2b);
    __nv_bfloat16* wv1t;  cudaGetSymbolAddress((void**)&wv1t, g_Wv1t);
    __nv_bfloat16* wv2t;  cudaGetSymbolAddress((void**)&wv2t, g_Wv2t);

    dim3 g3(HVV / 128, NROWS / 128);
    bf16gemm_kernel<3, HVV, DD><<<g3, 256>>>(resb, wv1t, bv1,
                                             nullptr, nullptr, nullptr, nullptr);

    dim3 g4(DD / 128, NROWS / 128);
    bf16gemm_kernel<4, DD, HVV><<<g4, 256>>>(h2b, wv2t, bv2,
                                             x, gate, oscal, out);
}

// round 15
// speedup vs baseline: 3.3121x; 1.1444x over previous
#include <cuda_runtime.h>
#include <cuda_bf16.h>
#include <math.h>

// Problem constants (fixed shapes)
#define NROWS (8 * 4096)   // B*T
#define DD    1024
#define HCC   256
#define HVV   256
#define NTT   64
#define NCC   8
#define TPCC  8
#define GGG   16
#define TTT   4096

// ---------------- scratch (static device globals; no runtime allocation) ----
__device__ float         g_xn[(size_t)NROWS * DD];
__device__ float         g_d[(size_t)NROWS * DD];       // out_sp (pre-vortex)
__device__ float         g_h[(size_t)NROWS * HCC];
__device__ __nv_bfloat16 g_ah[(size_t)NROWS * DD];      // hi(gauge(xn))
__device__ __nv_bfloat16 g_al[(size_t)NROWS * DD];      // lo(gauge(xn))
__device__ __nv_bfloat16 g_resb[(size_t)NROWS * DD];    // res in bf16 (GEMM3 A)
__device__ __nv_bfloat16 g_h2b[(size_t)NROWS * HVV];    // gelu(h2) bf16 (GEMM4 A)
__device__ __nv_bfloat16 g_Wc1h[HCC * DD];              // [256][1024] n-major hi
__device__ __nv_bfloat16 g_Wc1l[HCC * DD];              // [256][1024] n-major lo
__device__ __nv_bfloat16 g_Wv1t[HVV * DD];              // [256][1024] n-major
__device__ __nv_bfloat16 g_Wv2t[DD * HVV];              // [1024][256] n-major
__device__ int           g_tidx[NROWS];
__device__ float         g_tw[NROWS];
__device__ unsigned      g_sigbits[NTT * 32];
__device__ signed char   g_csig[NCC * DD];

__device__ __forceinline__ float bspline(float t) {
    t = fabsf(t);
    if (t < 1.0f) return (2.0f / 3.0f) - t * t + 0.5f * t * t * t;
    if (t < 2.0f) { float u = 2.0f - t; return (1.0f / 6.0f) * u * u * u; }
    return 0.0f;
}

__device__ __forceinline__ float gelu_exact(float v) {
    return 0.5f * v * (1.0f + erff(v * 0.70710678118654752f));
}

__device__ __forceinline__ void mma16816(float* d, const unsigned* a,
                                         const unsigned* b) {
    asm volatile(
        "mma.sync.aligned.m16n8k16.row.col.f32.bf16.bf16.f32 "
        "{%0,%1,%2,%3}, {%4,%5,%6,%7}, {%8,%9}, {%0,%1,%2,%3};\n"
        : "+f"(d[0]), "+f"(d[1]), "+f"(d[2]), "+f"(d[3])
        : "r"(a[0]), "r"(a[1]), "r"(a[2]), "r"(a[3]), "r"(b[0]), "r"(b[1]));
}

__device__ __forceinline__ unsigned smem_u32(const void* p) {
    return (unsigned)__cvta_generic_to_shared(p);
}
__device__ __forceinline__ void cp16(unsigned dst, const void* src) {
    asm volatile("cp.async.cg.shared.global [%0], [%1], 16;\n"
                 :: "r"(dst), "l"(src));
}
__device__ __forceinline__ void cp_commit() {
    asm volatile("cp.async.commit_group;\n");
}
__device__ __forceinline__ void cp_wait0() {
    asm volatile("cp.async.wait_group 0;\n" ::: "memory");
}
__device__ __forceinline__ void cp_wait1() {
    asm volatile("cp.async.wait_group 1;\n" ::: "memory");
}
__device__ __forceinline__ void ldsm4(unsigned& r0, unsigned& r1,
                                      unsigned& r2, unsigned& r3, unsigned a) {
    asm volatile("ldmatrix.sync.aligned.m8n8.x4.shared.b16 {%0,%1,%2,%3}, [%4];\n"
                 : "=r"(r0), "=r"(r1), "=r"(r2), "=r"(r3) : "r"(a));
}

// ---------------- prep: pack sign(directions) and csig ----------------------
__global__ void prep_kernel(const float* __restrict__ dirs) {
    int tid = threadIdx.x;
    for (int idx = tid; idx < NCC * DD; idx += blockDim.x) {
        int c = idx / DD, d = idx % DD;
        int s = 0;
        #pragma unroll
        for (int i = 0; i < TPCC; i++) {
            float v = dirs[(size_t)(c * TPCC + i) * DD + d];
            s += (v > 0.0f) ? 1 : ((v < 0.0f) ? -1 : 0);
        }
        g_csig[idx] = (signed char)((s > 0) - (s < 0));
    }
    int lane = tid & 31, wid = tid >> 5;
    int nw = blockDim.x >> 5;
    for (int q = wid; q < NTT * 32; q += nw) {
        int t = q >> 5, w = q & 31;
        float v = dirs[(size_t)t * DD + w * 32 + lane];
        unsigned m = __ballot_sync(0xFFFFFFFFu, v > 0.0f);
        if (lane == 0) g_sigbits[q] = m;
    }
}

// ------- weight conversion: Wv1/Wv2 -> bf16 transposed, Wc1 -> split --------
__global__ void convert_weights_kernel(const float* __restrict__ Wv1,
                                       const float* __restrict__ Wv2,
                                       const float* __restrict__ Wc1) {
    int i = blockIdx.x * blockDim.x + threadIdx.x;  // 0 .. 262143
    if (i < HVV * DD) {
        int n = i >> 10, k = i & 1023;
        g_Wv1t[i] = __float2bfloat16(Wv1[(size_t)k * HVV + n]);
        int n2 = i >> 8, k2 = i & 255;
        g_Wv2t[i] = __float2bfloat16(Wv2[(size_t)k2 * DD + n2]);
        float w = Wc1[(size_t)k * HCC + n];
        __nv_bfloat16 hi = __float2bfloat16(w);
        g_Wc1h[i] = hi;
        g_Wc1l[i] = __float2bfloat16(w - __bfloat162float(hi));
    }
}

// ---- LN + content + tile selection + gauge-split (1 row per block) ---------
__global__ __launch_bounds__(256) void ln_content_kernel(
    const float* __restrict__ x, const int* __restrict__ positions,
    const float* __restrict__ ln_g, const float* __restrict__ ln_b,
    const float* __restrict__ gscale, const float* __restrict__ gshift)
{
    __shared__ float    s_xn[DD];
    __shared__ unsigned s_bits[NTT * 32];
    __shared__ signed char s_csig[NCC * DD];
    __shared__ float s_content[NTT];
    __shared__ float s_cs[NCC];
    __shared__ float s_red[8], s_red2[8];
    __shared__ float s_mu, s_rstd;
    __shared__ int   s_ti;

    int row = blockIdx.x;
    int tid = threadIdx.x, lane = tid & 31, wid = tid >> 5;
    const float* xr = x + (size_t)row * DD;

    float4 xv = *(const float4*)(xr + tid * 4);
    float ps  = xv.x + xv.y + xv.z + xv.w;
    float ps2 = xv.x * xv.x + xv.y * xv.y + xv.z * xv.z + xv.w * xv.w;
    #pragma unroll
    for (int o = 16; o; o >>= 1) {
        ps  += __shfl_xor_sync(0xFFFFFFFFu, ps, o);
        ps2 += __shfl_xor_sync(0xFFFFFFFFu, ps2, o);
    }
    if (lane == 0) { s_red[wid] = ps; s_red2[wid] = ps2; }
    __syncthreads();
    if (tid == 0) {
        float s = 0.0f, s2 = 0.0f;
        #pragma unroll
        for (int i = 0; i < 8; i++) { s += s_red[i]; s2 += s_red2[i]; }
        float mu  = s * (1.0f / DD);
        float var = s2 * (1.0f / DD) - mu * mu;
        s_mu = mu;
        s_rstd = rsqrtf(var + 1e-5f);
    }
    for (int i = tid; i < NTT * 32; i += 256) s_bits[i] = __ldg(&g_sigbits[i]);
    for (int i = tid; i < (NCC * DD) / 16; i += 256)
        ((int4*)s_csig)[i] = __ldg(((const int4*)g_csig) + i);
    __syncthreads();

    float mu = s_mu, rstd = s_rstd;
    float4 g4 = *(const float4*)(ln_g + tid * 4);
    float4 b4 = *(const float4*)(ln_b + tid * 4);
    float4 nv;
    nv.x = (xv.x - mu) * rstd * g4.x + b4.x;
    nv.y = (xv.y - mu) * rstd * g4.y + b4.y;
    nv.z = (xv.z - mu) * rstd * g4.z + b4.z;
    nv.w = (xv.w - mu) * rstd * g4.w + b4.w;
    *(float4*)(s_xn + tid * 4) = nv;
    *(float4*)(g_xn + (size_t)row * DD + tid * 4) = nv;
    __syncthreads();

    // content: i-outer loop, 8 accumulators; bit words are warp-broadcast LDS
    {
        float accs[8];
        #pragma unroll
        for (int j = 0; j < 8; j++) accs[j] = 0.0f;
        for (int i = 0; i < 32; i++) {
            float v = s_xn[i * 32 + lane];
            #pragma unroll
            for (int j = 0; j < 8; j++) {
                unsigned w = s_bits[(wid * 8 + j) * 32 + i];
                accs[j] += ((w >> lane) & 1u) ? v : -v;
            }
        }
        #pragma unroll
        for (int j = 0; j < 8; j++) {
            float a = accs[j];
            #pragma unroll
            for (int o = 16; o; o >>= 1) a += __shfl_xor_sync(0xFFFFFFFFu, a, o);
            if (lane == 0) s_content[wid * 8 + j] = a;
        }
    }
    {
        float acc = 0.0f;
        const signed char* cp = s_csig + wid * DD;
        for (int i = lane; i < DD; i += 32) acc += s_xn[i] * (float)cp[i];
        #pragma unroll
        for (int o = 16; o; o >>= 1) acc += __shfl_xor_sync(0xFFFFFFFFu, acc, o);
        if (lane == 0) s_cs[wid] = acc;
    }
    __syncthreads();

    if (tid == 0) {
        float p = (float)positions[row & (TTT - 1)];
        float bestc = -INFINITY; int cidx = 0;
        #pragma unroll
        for (int c = 0; c < NCC; c++) {
            float arg = (p * (8.0f / 4096.0f) - (float)c) * 4.0f;
            float v = s_cs[c] * bspline(arg);
            if (v > bestc) { bestc = v; cidx = c; }
        }
        float bestt = -INFINITY; int ti = cidx * TPCC;
        for (int t = cidx * TPCC; t < cidx * TPCC + TPCC; t++) {
            float arg = (p * (64.0f / 4096.0f) - (float)t) * 0.5f;
            float v = s_content[t] * bspline(arg);
            if (v > bestt) { bestt = v; ti = t; }
        }
        g_tidx[row] = ti;
        g_tw[row] = bestt;
        s_ti = ti;
    }
    __syncthreads();

    // gauge transform + hi/lo bf16 split (registers, no smem hazard)
    {
        int ti = s_ti;
        int d = tid * 4;
        size_t base = (size_t)row * DD + d;
        size_t tb = (size_t)ti * DD + d;
        float4 gs = *(const float4*)(gscale + tb);
        float4 gb = *(const float4*)(gshift + tb);
        float v0 = nv.x * gs.x + gb.x;
        float v1 = nv.y * gs.y + gb.y;
        float v2 = nv.z * gs.z + gb.z;
        float v3 = nv.w * gs.w + gb.w;
        __nv_bfloat16 h0 = __float2bfloat16(v0), h1 = __float2bfloat16(v1);
        __nv_bfloat16 h2 = __float2bfloat16(v2), h3 = __float2bfloat16(v3);
        __nv_bfloat162 hp0; hp0.x = h0; hp0.y = h1;
        __nv_bfloat162 hp1; hp1.x = h2; hp1.y = h3;
        *(__nv_bfloat162*)(g_ah + base)     = hp0;
        *(__nv_bfloat162*)(g_ah + base + 2) = hp1;
        __nv_bfloat162 lp0 = __floats2bfloat162_rn(v0 - __bfloat162float(h0),
                                                   v1 - __bfloat162float(h1));
        __nv_bfloat162 lp1 = __floats2bfloat162_rn(v2 - __bfloat162float(h2),
                                                   v3 - __bfloat162float(h3));
        *(__nv_bfloat162*)(g_al + base)     = lp0;
        *(__nv_bfloat162*)(g_al + base + 2) = lp1;
    }
}

// ---------------- row finisher: ab GEMV, spline, out_sp + res(bf16) ---------
__global__ __launch_bounds__(256) void rowfin_kernel(
    const float* __restrict__ Wc2, const float* __restrict__ bc2,
    const float* __restrict__ spline_coeffs, const float* __restrict__ sscale,
    const float* __restrict__ gscale, const float* __restrict__ gshift,
    const float* __restrict__ dirs)
{
    int row = blockIdx.x;
    int tid = threadIdx.x, lane = tid & 31, wid = tid >> 5;
    __shared__ float s_par[16];
    __shared__ float s_sp;
    int ti = g_tidx[row];

    // GEMV distributed across all 8 warps: one element per lane
    {
        int j = tid;  // 0..255
        float hv = g_h[(size_t)row * HCC + j];
        float a0 = hv * Wc2[j * 2 + 0];
        float a1 = hv * Wc2[j * 2 + 1];
        #pragma unroll
        for (int o = 16; o; o >>= 1) {
            a0 += __shfl_xor_sync(0xFFFFFFFFu, a0, o);
            a1 += __shfl_xor_sync(0xFFFFFFFFu, a1, o);
        }
        if (lane == 0) { s_par[wid] = a0; s_par[8 + wid] = a1; }
    }
    __syncthreads();
    if (tid == 0) {
        float a0 = 0.0f, a1 = 0.0f;
        #pragma unroll
        for (int i = 0; i < 8; i++) { a0 += s_par[i]; a1 += s_par[8 + i]; }
        float a = tanhf(a0 + bc2[0]);
        float b = tanhf(a1 + bc2[1]);
        int ia = (int)((a + 1.0f) * 8.0f); ia = ia < 0 ? 0 : (ia > GGG - 1 ? GGG - 1 : ia);
        int ib = (int)((b + 1.0f) * 8.0f); ib = ib < 0 ? 0 : (ib > GGG - 1 ? GGG - 1 : ib);
        const float* cp = spline_coeffs + (((size_t)ti * GGG + ia) * GGG + ib) * 3;
        float c0 = cp[0] > 0.3f ? 1.0f : (cp[0] < -0.3f ? -1.0f : 0.0f);
        float c1 = cp[1] > 0.3f ? 1.0f : (cp[1] < -0.3f ? -1.0f : 0.0f);
        float c2 = cp[2] > 0.3f ? 1.0f : (cp[2] < -0.3f ? -1.0f : 0.0f);
        float la = (a + 1.0f - (float)ia * 0.125f) * 8.0f;
        float lb = (b + 1.0f - (float)ib * 0.125f) * 8.0f;
        s_sp = (c0 + c1 * la + c2 * lb) * sscale[ti] * g_tw[row];
    }
    __syncthreads();
    float sp = s_sp;
    int d = tid * 4;
    size_t base = (size_t)row * DD + d;
    size_t tb = (size_t)ti * DD + d;
    float4 dir = *(const float4*)(dirs + tb);
    float4 gs  = *(const float4*)(gscale + tb);
    float4 gb  = *(const float4*)(gshift + tb);
    float4 xn  = *(const float4*)(g_xn + base);
    float4 o;
    o.x = (sp * dir.x - gb.x) / (gs.x + 1e-6f);
    o.y = (sp * dir.y - gb.y) / (gs.y + 1e-6f);
    o.z = (sp * dir.z - gb.z) / (gs.z + 1e-6f);
    o.w = (sp * dir.w - gb.w) / (gs.w + 1e-6f);
    *(float4*)(g_d + base) = o;
    __nv_bfloat162 r01 = __floats2bfloat162_rn(xn.x - o.x, xn.y - o.y);
    __nv_bfloat162 r23 = __floats2bfloat162_rn(xn.z - o.z, xn.w - o.w);
    *(__nv_bfloat162*)(g_resb + base)     = r01;
    *(__nv_bfloat162*)(g_resb + base + 2) = r23;
}

// ---- GEMM1 split-bf16 3-product: h = gelu(Ah*Wh + Al*Wh + Ah*Wl + bias) ----
// cp.async staging + ldmatrix fragments; 2 CTAs/SM target
__global__ __launch_bounds__(256, 2) void gemm1split_kernel(
    const float* __restrict__ bias)
{
    constexpr int N = HCC, K = DD, KP = 40;
    __shared__ alignas(16) __nv_bfloat16 Ahs[128 * KP];
    __shared__ alignas(16) __nv_bfloat16 Als[128 * KP];
    __shared__ alignas(16) __nv_bfloat16 Bhs[128 * KP];
    __shared__ alignas(16) __nv_bfloat16 Bls[128 * KP];

    int tid = threadIdx.x;
    int lane = tid & 31, wid = tid >> 5;
    int wm = (wid >> 2) * 64;
    int wn = (wid & 3) * 32;
    int bm = blockIdx.y * 128, bn = blockIdx.x * 128;

    int lrow = tid >> 1, lcol = (tid & 1) * 16;
    const __nv_bfloat16* Ahp = g_ah + (size_t)(bm + lrow) * K + lcol;
    const __nv_bfloat16* Alp = g_al + (size_t)(bm + lrow) * K + lcol;
    const __nv_bfloat16* Bhp = g_Wc1h + (size_t)(bn + lrow) * K + lcol;
    const __nv_bfloat16* Blp = g_Wc1l + (size_t)(bn + lrow) * K + lcol;

    unsigned sAh = smem_u32(Ahs), sAl = smem_u32(Als);
    unsigned sBh = smem_u32(Bhs), sBl = smem_u32(Bls);
    unsigned stoff = (unsigned)(lrow * KP + lcol) * 2u;
    int frow = lane & 15;
    int fhi = (lane >> 4) * 8;

    float acc[4][4][4];
    #pragma unroll
    for (int mi = 0; mi < 4; mi++)
        #pragma unroll
        for (int ni = 0; ni < 4; ni++)
            #pragma unroll
            for (int e = 0; e < 4; e++) acc[mi][ni][e] = 0.0f;

    for (int k0 = 0; k0 < K; k0 += 32) {
        cp16(sAh + stoff,      Ahp + k0);
        cp16(sAh + stoff + 16, Ahp + k0 + 8);
        cp16(sAl + stoff,      Alp + k0);
        cp16(sAl + stoff + 16, Alp + k0 + 8);
        cp16(sBh + stoff,      Bhp + k0);
        cp16(sBh + stoff + 16, Bhp + k0 + 8);
        cp16(sBl + stoff,      Blp + k0);
        cp16(sBl + stoff + 16, Blp + k0 + 8);
        cp_commit();
        cp_wait0();
        __syncthreads();

        #pragma unroll
        for (int s = 0; s < 2; s++) {
            unsigned fco = (unsigned)(s * 16 + fhi);
            unsigned bh[4][2], bl[4][2];
            #pragma unroll
            for (int p = 0; p < 2; p++) {
                unsigned roff = (unsigned)((wn + p * 16 + frow) * KP) + fco;
                ldsm4(bh[2 * p][0], bh[2 * p + 1][0],
                      bh[2 * p][1], bh[2 * p + 1][1], sBh + roff * 2u);
                ldsm4(bl[2 * p][0], bl[2 * p + 1][0],
                      bl[2 * p][1], bl[2 * p + 1][1], sBl + roff * 2u);
            }
            #pragma unroll
            for (int mi = 0; mi < 4; mi++) {
                unsigned aoff = (unsigned)((wm + mi * 16 + frow) * KP) + fco;
                unsigned ah[4], al[4];
                ldsm4(ah[0], ah[1], ah[2], ah[3], sAh + aoff * 2u);
                ldsm4(al[0], al[1], al[2], al[3], sAl + aoff * 2u);
                #pragma unroll
                for (int ni = 0; ni < 4; ni++) {
                    mma16816(acc[mi][ni], ah, bh[ni]);
                    mma16816(acc[mi][ni], al, bh[ni]);
                    mma16816(acc[mi][ni], ah, bl[ni]);
                }
            }
        }
        __syncthreads();
    }

    int g = lane >> 2, t4 = lane & 3;
    #pragma unroll
    for (int mi = 0; mi < 4; mi++) {
        #pragma unroll
        for (int ni = 0; ni < 4; ni++) {
            int r0 = bm + wm + mi * 16 + g;
            int c  = bn + wn + ni * 8 + 2 * t4;
            float b0 = bias[c], b1 = bias[c + 1];
            float2 v0, v1;
            v0.x = gelu_exact(acc[mi][ni][0] + b0);
            v0.y = gelu_exact(acc[mi][ni][1] + b1);
            v1.x = gelu_exact(acc[mi][ni][2] + b0);
            v1.y = gelu_exact(acc[mi][ni][3] + b1);
            *(float2*)(g_h + (size_t)r0 * N + c)       = v0;
            *(float2*)(g_h + (size_t)(r0 + 8) * N + c) = v1;
        }
    }
}

// ---- bf16 tensor-core GEMM, 2-stage cp.async pipeline ----------------------
// MODE 3: g_h2b = bf16(gelu(g_resb @ Wv1t^T + bv1))       [N=256,  K=1024]
// MODE 4: out = x + os*(g_d + gv*(g_h2b @ Wv2t^T + bv2))  [N=1024, K=256]
template <int MODE, int N, int K>
__global__ __launch_bounds__(256, 2) void bf16gemm_kernel(
    const __nv_bfloat16* __restrict__ A,   // [NROWS][K]
    const __nv_bfloat16* __restrict__ Bt,  // [N][K]
    const float* __restrict__ bias,
    const float* __restrict__ x, const float* __restrict__ gate,
    const float* __restrict__ oscale, float* __restrict__ out)
{
    constexpr int KP = 40;
    constexpr int NIT = K / 32;
    __shared__ alignas(16) __nv_bfloat16 As[2][128 * KP];
    __shared__ alignas(16) __nv_bfloat16 Bs[2][128 * KP];

    int tid = threadIdx.x;
    int lane = tid & 31, wid = tid >> 5;
    int wm = (wid >> 2) * 64;
    int wn = (wid & 3) * 32;
    int bm = blockIdx.y * 128, bn = blockIdx.x * 128;

    int lrow = tid >> 1, lcol = (tid & 1) * 16;
    const __nv_bfloat16* Ap = A + (size_t)(bm + lrow) * K + lcol;
    const __nv_bfloat16* Bp = Bt + (size_t)(bn + lrow) * K + lcol;

    unsigned sA[2] = { smem_u32(As[0]), smem_u32(As[1]) };
    unsigned sB[2] = { smem_u32(Bs[0]), smem_u32(Bs[1]) };
    unsigned stoff = (unsigned)(lrow * KP + lcol) * 2u;
    int frow = lane & 15;
    int fhi = (lane >> 4) * 8;

    float acc[4][4][4];
    #pragma unroll
    for (int mi = 0; mi < 4; mi++)
        #pragma unroll
        for (int ni = 0; ni < 4; ni++)
            #pragma unroll
            for (int e = 0; e < 4; e++) acc[mi][ni][e] = 0.0f;

    // prologue: stage 0
    cp16(sA[0] + stoff,      Ap);
    cp16(sA[0] + stoff + 16, Ap + 8);
    cp16(sB[0] + stoff,      Bp);
    cp16(sB[0] + stoff + 16, Bp + 8);
    cp_commit();

    for (int it = 0; it < NIT; it++) {
        int cur = it & 1;
        if (it + 1 < NIT) {
            int nxt = cur ^ 1;
            int kn = (it + 1) * 32;
            cp16(sA[nxt] + stoff,      Ap + kn);
            cp16(sA[nxt] + stoff + 16, Ap + kn + 8);
            cp16(sB[nxt] + stoff,      Bp + kn);
            cp16(sB[nxt] + stoff + 16, Bp + kn + 8);
            cp_commit();
            cp_wait1();
        } else {
            cp_wait0();
        }
        __syncthreads();

        #pragma unroll
        for (int s = 0; s < 2; s++) {
            unsigned fco = (unsigned)(s * 16 + fhi);
            unsigned bfr[4][2];
            #pragma unroll
            for (int p = 0; p < 2; p++) {
                unsigned roff = (unsigned)((wn + p * 16 + frow) * KP) + fco;
                ldsm4(bfr[2 * p][0], bfr[2 * p + 1][0],
                      bfr[2 * p][1], bfr[2 * p + 1][1], sB[cur] + roff * 2u);
            }
            #pragma unroll
            for (int mi = 0; mi < 4; mi++) {
                unsigned aoff = (unsigned)((wm + mi * 16 + frow) * KP) + fco;
                unsigned afr[4];
                ldsm4(afr[0], afr[1], afr[2], afr[3], sA[cur] + aoff * 2u);
                #pragma unroll
                for (int ni = 0; ni < 4; ni++)
                    mma16816(acc[mi][ni], afr, bfr[ni]);
            }
        }
        __syncthreads();
    }

    float gv = 0.0f, os = 0.0f;
    if (MODE == 4) {
        gv = 1.0f / (1.0f + expf(-gate[0]));
        os = oscale[0];
    }
    int g = lane >> 2, t4 = lane & 3;
    #pragma unroll
    for (int mi = 0; mi < 4; mi++) {
        #pragma unroll
        for (int ni = 0; ni < 4; ni++) {
            int r0 = bm + wm + mi * 16 + g;
            int c  = bn + wn + ni * 8 + 2 * t4;
            float b0 = bias[c], b1 = bias[c + 1];
            if (MODE == 3) {
                float v0 = gelu_exact(acc[mi][ni][0] + b0);
                float v1 = gelu_exact(acc[mi][ni][1] + b1);
                float v2 = gelu_exact(acc[mi][ni][2] + b0);
                float v3 = gelu_exact(acc[mi][ni][3] + b1);
                *(__nv_bfloat162*)(g_h2b + (size_t)r0 * N + c) =
                    __floats2bfloat162_rn(v0, v1);
                *(__nv_bfloat162*)(g_h2b + (size_t)(r0 + 8) * N + c) =
                    __floats2bfloat162_rn(v2, v3);
            } else {
                size_t i0 = (size_t)r0 * N + c;
                size_t i1 = (size_t)(r0 + 8) * N + c;
                float2 x0 = *(const float2*)(x + i0);
                float2 x1 = *(const float2*)(x + i1);
                float2 d0 = *(const float2*)(g_d + i0);
                float2 d1 = *(const float2*)(g_d + i1);
                float2 o0, o1;
                o0.x = x0.x + os * (d0.x + gv * (acc[mi][ni][0] + b0));
                o0.y = x0.y + os * (d0.y + gv * (acc[mi][ni][1] + b1));
                o1.x = x1.x + os * (d1.x + gv * (acc[mi][ni][2] + b0));
                o1.y = x1.y + os * (d1.y + gv * (acc[mi][ni][3] + b1));
                *(float2*)(out + i0) = o0;
                *(float2*)(out + i1) = o1;
            }
        }
    }
}

// ---------------- launcher --------------------------------------------------
extern "C" void kernel_launch(void* const* d_in, const int* in_sizes, int n_in,
                              void* d_out, int out_size) {
    const float* x     = (const float*)d_in[0];
    const int*   pos   = (const int*)d_in[1];
    const float* ln_g  = (const float*)d_in[2];
    const float* ln_b  = (const float*)d_in[3];
    const float* Wc1   = (const float*)d_in[4];
    const float* bc1   = (const float*)d_in[5];
    const float* Wc2   = (const float*)d_in[6];
    const float* bc2   = (const float*)d_in[7];
    const float* dirs  = (const float*)d_in[8];
    const float* spl   = (const float*)d_in[9];
    const float* sscal = (const float*)d_in[10];
    const float* gsc   = (const float*)d_in[11];
    const float* gsh   = (const float*)d_in[12];
    const float* Wv1   = (const float*)d_in[13];
    const float* bv1   = (const float*)d_in[14];
    const float* Wv2   = (const float*)d_in[15];
    const float* bv2   = (const float*)d_in[16];
    const float* gate  = (const float*)d_in[17];
    const float* oscal = (const float*)d_in[18];
    float* out = (float*)d_out;

    prep_kernel<<<1, 256>>>(dirs);
    convert_weights_kernel<<<(HVV * DD + 255) / 256, 256>>>(Wv1, Wv2, Wc1);
    ln_content_kernel<<<NROWS, 256>>>(x, pos, ln_g, ln_b, gsc, gsh);

    dim3 g1(HCC / 128, NROWS / 128);
    gemm1split_kernel<<<g1, 256>>>(bc1);

    rowfin_kernel<<<NROWS, 256>>>(Wc2, bc2, spl, sscal, gsc, gsh, dirs);

    __nv_bfloat16* resb;  cudaGetSymbolAddress((void**)&resb, g_resb);
    __nv_bfloat16* h2b;   cudaGetSymbolAddress((void**)&h2b, g_h2b);
    __nv_bfloat16* wv1t;  cudaGetSymbolAddress((void**)&wv1t, g_Wv1t);
    __nv_bfloat16* wv2t;  cudaGetSymbolAddress((void**)&wv2t, g_Wv2t);

    dim3 g3(HVV / 128, NROWS / 128);
    bf16gemm_kernel<3, HVV, DD><<<g3, 256>>>(resb, wv1t, bv1,
                                             nullptr, nullptr, nullptr, nullptr);

    dim3 g4(DD / 128, NROWS / 128);
    bf16gemm_kernel<4, DD, HVV><<<g4, 256>>>(h2b, wv2t, bv2,
                                             x, gate, oscal, out);
}